// round 15
// baseline (speedup 1.0000x reference)
#include <cuda_runtime.h>
#include <cstdint>

// Problem constants
#define H_   128
#define W_   128
#define BATCH 8
#define CIN  256
#define HWSZ (H_*W_)          // 16384
#define KKT  49

#define ASTR 108   // im2col row stride (floats): conflict-free A-frag loads
#define BSTR 152   // weight row stride
#define CSTR 153   // C row stride: odd -> conflict-free epilogue reads
#define KPAD 104   // 13 k-tiles of 8 (98 real)
#define NPAD 152   // 19 n-tiles of 8 (147 real)

// Scratch (allocation-free rule: __device__ globals)
__device__ float g_part[BATCH * 2 * 2 * HWSZ];  // [b][half][{sum,max}][hw]
__device__ float g_att [BATCH * 2 * HWSZ];      // [b][{avg,max}][h][w]
__device__ float g_attn[BATCH * HWSZ];          // final sigmoid attention

__device__ __forceinline__ float sigmoidf_(float v) {
    return 1.f / (1.f + __expf(-v));
}
__device__ __forceinline__ uint32_t to_tf32(float v) {
    uint32_t r; asm("cvt.rna.tf32.f32 %0, %1;" : "=r"(r) : "f"(v)); return r;
}

// ---------------------------------------------------------------------------
// K1a: partial channel mean+max (split-C x2, x8-batched loads).
// ---------------------------------------------------------------------------
__global__ __launch_bounds__(256) void reduce_part_kernel(const float* __restrict__ x) {
    int i = blockIdx.x * 256 + threadIdx.x;
    int hw4  = i & 4095;
    int rest = i >> 12;
    int b    = rest >> 1;
    int half = rest & 1;
    const float4* xp = (const float4*)(x + (size_t)b * CIN * HWSZ)
                       + (size_t)half * 128 * (HWSZ / 4) + hw4;
    float4 s = make_float4(0.f, 0.f, 0.f, 0.f);
    const float NEG = -3.402823466e38f;
    float4 m = make_float4(NEG, NEG, NEG, NEG);
    #pragma unroll 1
    for (int c = 0; c < 128; c += 8) {
        float4 v[8];
        #pragma unroll
        for (int u = 0; u < 8; ++u) v[u] = __ldg(xp + (c + u) * (HWSZ / 4));
        #pragma unroll
        for (int u = 0; u < 8; ++u) {
            s.x += v[u].x; s.y += v[u].y; s.z += v[u].z; s.w += v[u].w;
            m.x = fmaxf(m.x, v[u].x); m.y = fmaxf(m.y, v[u].y);
            m.z = fmaxf(m.z, v[u].z); m.w = fmaxf(m.w, v[u].w);
        }
    }
    float4* pp = (float4*)(g_part + ((b * 2 + half) * 2) * HWSZ);
    pp[hw4]              = s;
    pp[(HWSZ / 4) + hw4] = m;
}

// ---------------------------------------------------------------------------
// K1b: combine halves into g_att.
// ---------------------------------------------------------------------------
__global__ __launch_bounds__(256) void reduce_comb_kernel() {
    int i = blockIdx.x * 256 + threadIdx.x;
    int hw4 = i & 4095;
    int b   = i >> 12;
    const float4* p0 = (const float4*)(g_part + ((b * 2 + 0) * 2) * HWSZ);
    const float4* p1 = (const float4*)(g_part + ((b * 2 + 1) * 2) * HWSZ);
    float4 s0 = p0[hw4],              s1 = p1[hw4];
    float4 m0 = p0[(HWSZ / 4) + hw4], m1 = p1[(HWSZ / 4) + hw4];
    const float inv = 1.f / 256.f;
    float4 s, m;
    s.x = (s0.x + s1.x) * inv; s.y = (s0.y + s1.y) * inv;
    s.z = (s0.z + s1.z) * inv; s.w = (s0.w + s1.w) * inv;
    m.x = fmaxf(m0.x, m1.x); m.y = fmaxf(m0.y, m1.y);
    m.z = fmaxf(m0.z, m1.z); m.w = fmaxf(m0.w, m1.w);
    ((float4*)(g_att + b * 2 * HWSZ))[hw4]        = s;
    ((float4*)(g_att + b * 2 * HWSZ + HWSZ))[hw4] = m;
}

// ---------------------------------------------------------------------------
// K2: tensor-core deform.  Per CTA: one image row (b, h) = 128 pixels.
// GEMM via mma.sync.m16n8k8.tf32: A = im2col patch [128 x 104],
// B = weights [104 x 152] (n<98: offset ch, 98..146: mod ch), C -> SMEM,
// then bilinear-sampling epilogue (2 threads/pixel) -> sigmoid -> g_attn.
// ---------------------------------------------------------------------------
__global__ __launch_bounds__(256) void deform_mma_kernel(
    const float* __restrict__ offw, const float* __restrict__ offb,
    const float* __restrict__ modw, const float* __restrict__ modb,
    const float* __restrict__ dcw)
{
    extern __shared__ float sm[];
    float* As   = sm;                          // [128][ASTR] (tf32 bits)
    float* Bs   = As + 128 * ASTR;             // [104][BSTR] (tf32 bits)
    float* Cs   = Bs + KPAD * BSTR;            // [128][CSTR] fp32
    float* part = Cs + 128 * CSTR;             // [256]
    float* sdc  = part + 256;                  // dcw   [98]
    float* sob  = sdc + 98;                    // offb  [98]
    float* smb  = sob + 98;                    // modb  [49]

    const int tid = threadIdx.x;
    const int bid = blockIdx.x;                // b*128 + h
    const int b   = bid >> 7;
    const int h   = bid & 127;
    const float* __restrict__ a0 = g_att + b * 2 * HWSZ;
    const float* __restrict__ a1 = a0 + HWSZ;

    if (tid < 98) sdc[tid] = dcw[tid];
    if (tid < 98) sob[tid] = offb[tid];
    if (tid < 49) smb[tid] = modb[tid];

    // B fill: Bs[k][n]; offw is [98][98] (=[2KK][2*7*7]), modw [49][98].
    for (int idx = tid; idx < KPAD * NPAD; idx += 256) {
        int n = idx / KPAD, k = idx - n * KPAD;
        float v = 0.f;
        if (k < 98) {
            if (n < 98)       v = offw[n * 98 + k];
            else if (n < 147) v = modw[(n - 98) * 98 + k];
        }
        ((uint32_t*)Bs)[k * BSTR + n] = to_tf32(v);
    }
    // A fill (im2col, zero-padded): As[p][k], k = c*49 + t, t=(ki,kj).
    for (int idx = tid; idx < KPAD * 128; idx += 256) {
        int k = idx >> 7, p = idx & 127;
        float v = 0.f;
        if (k < 98) {
            int c = k / 49, t = k - c * 49;
            int yy = h + t / 7 - 3, xx = p + t % 7 - 3;
            if ((unsigned)yy < (unsigned)H_ && (unsigned)xx < (unsigned)W_)
                v = (c ? a1 : a0)[(yy << 7) + xx];
        }
        ((uint32_t*)As)[p * ASTR + k] = to_tf32(v);
    }
    __syncthreads();

    // MMA: each warp owns 16 pixel rows x all 19 n-tiles.
    {
        const int wid = tid >> 5, lane = tid & 31;
        const int g = lane >> 2, tg = lane & 3;
        const int rbase = wid * 16;
        float c[19][4];
        #pragma unroll
        for (int nt = 0; nt < 19; ++nt)
            c[nt][0] = c[nt][1] = c[nt][2] = c[nt][3] = 0.f;
        const uint32_t* Au = (const uint32_t*)As;
        const uint32_t* Bu = (const uint32_t*)Bs;
        #pragma unroll 1
        for (int kt = 0; kt < 13; ++kt) {
            int col = kt * 8 + tg;
            uint32_t A0 = Au[(rbase + g)     * ASTR + col];
            uint32_t A1 = Au[(rbase + g + 8) * ASTR + col];
            uint32_t A2 = Au[(rbase + g)     * ASTR + col + 4];
            uint32_t A3 = Au[(rbase + g + 8) * ASTR + col + 4];
            #pragma unroll
            for (int nt = 0; nt < 19; ++nt) {
                uint32_t B0 = Bu[(kt * 8 + tg)     * BSTR + nt * 8 + g];
                uint32_t B1 = Bu[(kt * 8 + tg + 4) * BSTR + nt * 8 + g];
                asm volatile(
                    "mma.sync.aligned.m16n8k8.row.col.f32.tf32.tf32.f32 "
                    "{%0,%1,%2,%3}, {%4,%5,%6,%7}, {%8,%9}, {%0,%1,%2,%3};"
                    : "+f"(c[nt][0]), "+f"(c[nt][1]), "+f"(c[nt][2]), "+f"(c[nt][3])
                    : "r"(A0), "r"(A1), "r"(A2), "r"(A3), "r"(B0), "r"(B1));
            }
        }
        // C -> SMEM.  c0:(row=g, n=2*tg) c1:n+1 c2:(row=g+8) c3.
        #pragma unroll
        for (int nt = 0; nt < 19; ++nt) {
            int n0 = nt * 8 + tg * 2;
            Cs[(rbase + g)     * CSTR + n0]     = c[nt][0];
            Cs[(rbase + g)     * CSTR + n0 + 1] = c[nt][1];
            Cs[(rbase + g + 8) * CSTR + n0]     = c[nt][2];
            Cs[(rbase + g + 8) * CSTR + n0 + 1] = c[nt][3];
        }
    }
    __syncthreads();

    // Epilogue: 2 threads per pixel split j-range (0..24 / 25..48).
    {
        int p = tid & 127, half = tid >> 7;
        int j0 = half ? 25 : 0, j1 = half ? 49 : 25;
        const float* Cp = Cs + p * CSTR;
        float acc = 0.f;
        #pragma unroll 1
        for (int j = j0; j < j1; ++j) {
            float offy = Cp[2 * j]     + sob[2 * j];
            float offx = Cp[2 * j + 1] + sob[2 * j + 1];
            float mask = 2.f * sigmoidf_(Cp[98 + j] + smb[j]);

            float py = (float)(h + j / 7 - 3) + offy;
            float px = (float)(p + j % 7 - 3) + offx;
            float y0f = floorf(py), x0f = floorf(px);
            int   y0  = (int)y0f,  x0  = (int)x0f;
            float wy1 = py - y0f,  wx1 = px - x0f;
            float wy0 = 1.f - wy1, wx0 = 1.f - wx1;

            int  y0c = min(max(y0, 0), H_ - 1),     y1c = min(max(y0 + 1, 0), H_ - 1);
            int  x0c = min(max(x0, 0), W_ - 1),     x1c = min(max(x0 + 1, 0), W_ - 1);
            bool vy0 = (unsigned)y0 < (unsigned)H_, vy1 = (unsigned)(y0 + 1) < (unsigned)H_;
            bool vx0 = (unsigned)x0 < (unsigned)W_, vx1 = (unsigned)(x0 + 1) < (unsigned)W_;
            float f0 = (vy0 && vx0) ? wy0 * wx0 : 0.f;
            float f1 = (vy0 && vx1) ? wy0 * wx1 : 0.f;
            float f2 = (vy1 && vx0) ? wy1 * wx0 : 0.f;
            float f3 = (vy1 && vx1) ? wy1 * wx1 : 0.f;
            int o0 = (y0c << 7) + x0c, o1 = (y0c << 7) + x1c;
            int o2 = (y1c << 7) + x0c, o3 = (y1c << 7) + x1c;

            float s0 = f0 * __ldg(a0 + o0) + f1 * __ldg(a0 + o1)
                     + f2 * __ldg(a0 + o2) + f3 * __ldg(a0 + o3);
            float s1 = f0 * __ldg(a1 + o0) + f1 * __ldg(a1 + o1)
                     + f2 * __ldg(a1 + o2) + f3 * __ldg(a1 + o3);
            acc += mask * (sdc[j] * s0 + sdc[49 + j] * s1);
        }
        part[tid] = acc;
    }
    __syncthreads();
    if (tid < 128)
        g_attn[b * HWSZ + (h << 7) + tid] = sigmoidf_(part[tid] + part[tid + 128]);
}

// ---------------------------------------------------------------------------
// K3: out = x * attn, 8 channels/thread (round-8 measured-best form).
// ---------------------------------------------------------------------------
#define CPT 8
__global__ __launch_bounds__(256) void mul_kernel(const float* __restrict__ x,
                                                  float* __restrict__ out)
{
    int i = blockIdx.x * 256 + threadIdx.x;
    int hw4 = i & (HWSZ / 4 - 1);
    int bc  = i >> 12;
    int b    = bc >> 5;
    int cgrp = bc & 31;
    float4 av = *((const float4*)g_attn + b * (HWSZ / 4) + hw4);
    size_t base = ((size_t)b * CIN + (size_t)cgrp * CPT) * (HWSZ / 4) + hw4;
    #pragma unroll
    for (int c = 0; c < CPT; ++c) {
        float4 xv = __ldg((const float4*)x + base + c * (HWSZ / 4));
        float4 ov;
        ov.x = xv.x * av.x;
        ov.y = xv.y * av.y;
        ov.z = xv.z * av.z;
        ov.w = xv.w * av.w;
        ((float4*)out)[base + c * (HWSZ / 4)] = ov;
    }
}

// ---------------------------------------------------------------------------
extern "C" void kernel_launch(void* const* d_in, const int* in_sizes, int n_in,
                              void* d_out, int out_size)
{
    const float* x    = (const float*)d_in[0];
    const float* offw = (const float*)d_in[1];
    const float* offb = (const float*)d_in[2];
    const float* modw = (const float*)d_in[3];
    const float* modb = (const float*)d_in[4];
    const float* dcw  = (const float*)d_in[5];
    float* out = (float*)d_out;

    // 128*108 + 104*152 + 128*153 + 256 + 98 + 98 + 49 = 49717 floats
    const int SMEM_BYTES = 49717 * 4;  // 198868 B < 227KB cap
    cudaFuncSetAttribute(deform_mma_kernel,
                         cudaFuncAttributeMaxDynamicSharedMemorySize, SMEM_BYTES);

    reduce_part_kernel<<<(BATCH * 2 * (HWSZ / 4)) / 256, 256>>>(x);
    reduce_comb_kernel<<<(BATCH * (HWSZ / 4)) / 256, 256>>>();
    deform_mma_kernel<<<BATCH * H_, 256, SMEM_BYTES>>>(offw, offb, modw, modb, dcw);
    mul_kernel<<<(BATCH * (CIN / CPT) * (HWSZ / 4)) / 256, 256>>>(x, out);
}